// round 10
// baseline (speedup 1.0000x reference)
#include <cuda_runtime.h>
#include <math.h>

#define BB   64
#define SS   512
#define II   512
#define HH   1024
#define G4   4096
#define OO   512
#define BH   (BB*HH)          // 65536
#define OUT_ELEMS (BB*SS*OO)  // 16777216
#define NBLK 128

typedef unsigned long long u64;

// -------- scratch (device globals; allocation-free per rules) --------
__device__ float g_xg[(size_t)SS * BB * G4];   // 512 MB, reused for both layers
__device__ float g_y [(size_t)BB * SS * HH];   // 128 MB, y0 then y1 (in place)
__device__ float g_h [2 * BH + 64];            // double-buffered hidden state
__device__ unsigned g_bar;                     // grid barrier counter

// ---------------- f32x2 helpers (sm_103a packed fp32 pipe) ----------------
__device__ __forceinline__ void fma2(u64& d, u64 a, u64 b) {
    asm("fma.rn.f32x2 %0, %1, %2, %3;" : "=l"(d) : "l"(a), "l"(b), "l"(d));
}
__device__ __forceinline__ u64 splat2(float v) {
    u64 r; asm("mov.b64 %0, {%1, %1};" : "=l"(r) : "f"(v)); return r;
}
__device__ __forceinline__ float2 unpack2(u64 a) {
    float2 r; asm("mov.b64 {%0, %1}, %2;" : "=f"(r.x), "=f"(r.y) : "l"(a)); return r;
}
__device__ __forceinline__ float fast_sig(float x) {
    return __fdividef(1.f, 1.f + __expf(-x));
}
__device__ __forceinline__ float fast_tanh(float x) {
    return 2.f * fast_sig(2.f * x) - 1.f;
}

// no-op kernel: shifts the ncu capture window (-s 5 -c 1, kernel launches
// only) so launch #6 is the layer-0 LSTM kernel.
__global__ void noop_kernel() {}

// ---------------------------------------------------------------
// Tiled fp32 GEMM (round-7 shape): 128x128x16, 256 threads, 8x8
// micro-tile (row-pair packed f32x2), double-buffered smem.
// C[m][n] = sum_k A[rowmap(m)][k] * W[n][k] + ba[n] (+ bb[n])
// ---------------------------------------------------------------
__global__ __launch_bounds__(256, 1)
void gemm_kernel(const float* __restrict__ A, const float* __restrict__ W,
                 const float* __restrict__ ba, const float* __restrict__ bb,
                 float* __restrict__ C, int M, int N, int K, int mapA)
{
    __shared__ float As[2][16][132];
    __shared__ float Ws[2][16][132];

    const int tid = threadIdx.x;
    const int bm  = blockIdx.y * 128;
    const int bn  = blockIdx.x * 128;
    const int tx  = tid & 15;
    const int ty  = tid >> 4;
    const int row0  = ty * 8;
    const int col0a = tx * 4;
    const int col0b = 64 + tx * 4;

    const int idx0 = tid * 2;
    const int idx1 = tid * 2 + 1;
    const int lrA0 = idx0 >> 2, kqA0 = idx0 & 3;
    const int lrA1 = idx1 >> 2, kqA1 = idx1 & 3;

    int m0 = bm + lrA0, m1 = bm + lrA1;
    long ar0 = mapA ? ((long)(m0 & 63) * SS + (m0 >> 6)) : (long)m0;
    long ar1 = mapA ? ((long)(m1 & 63) * SS + (m1 >> 6)) : (long)m1;
    const float* Ap0 = A + ar0 * K;
    const float* Ap1 = A + ar1 * K;
    const float* Wp0 = W + (long)(bn + lrA0) * K;
    const float* Wp1 = W + (long)(bn + lrA1) * K;

    u64 acc2[4][8];
#pragma unroll
    for (int i = 0; i < 4; i++)
#pragma unroll
        for (int j = 0; j < 8; j++) acc2[i][j] = 0ull;

    const int nk = K >> 4;

    float4 av0 = *(const float4*)(Ap0 + kqA0 * 4);
    float4 av1 = *(const float4*)(Ap1 + kqA1 * 4);
    float4 wv0 = *(const float4*)(Wp0 + kqA0 * 4);
    float4 wv1 = *(const float4*)(Wp1 + kqA1 * 4);
    {
        As[0][kqA0*4+0][lrA0] = av0.x; As[0][kqA0*4+1][lrA0] = av0.y;
        As[0][kqA0*4+2][lrA0] = av0.z; As[0][kqA0*4+3][lrA0] = av0.w;
        As[0][kqA1*4+0][lrA1] = av1.x; As[0][kqA1*4+1][lrA1] = av1.y;
        As[0][kqA1*4+2][lrA1] = av1.z; As[0][kqA1*4+3][lrA1] = av1.w;
        Ws[0][kqA0*4+0][lrA0] = wv0.x; Ws[0][kqA0*4+1][lrA0] = wv0.y;
        Ws[0][kqA0*4+2][lrA0] = wv0.z; Ws[0][kqA0*4+3][lrA0] = wv0.w;
        Ws[0][kqA1*4+0][lrA1] = wv1.x; Ws[0][kqA1*4+1][lrA1] = wv1.y;
        Ws[0][kqA1*4+2][lrA1] = wv1.z; Ws[0][kqA1*4+3][lrA1] = wv1.w;
    }
    __syncthreads();

    for (int kt = 0; kt < nk; kt++) {
        const int cur = kt & 1;
        const int nxt = cur ^ 1;
        const bool more = (kt + 1) < nk;

        if (more) {
            int k0 = (kt + 1) << 4;
            av0 = *(const float4*)(Ap0 + k0 + kqA0 * 4);
            av1 = *(const float4*)(Ap1 + k0 + kqA1 * 4);
            wv0 = *(const float4*)(Wp0 + k0 + kqA0 * 4);
            wv1 = *(const float4*)(Wp1 + k0 + kqA1 * 4);
        }

#pragma unroll
        for (int k = 0; k < 16; k++) {
            ulonglong2 a01 = *(const ulonglong2*)&As[cur][k][row0];
            ulonglong2 a23 = *(const ulonglong2*)&As[cur][k][row0 + 4];
            float4 bA = *(const float4*)&Ws[cur][k][col0a];
            float4 bB = *(const float4*)&Ws[cur][k][col0b];
            u64 a2[4] = {a01.x, a01.y, a23.x, a23.y};
            u64 w2[8];
            w2[0] = splat2(bA.x); w2[1] = splat2(bA.y);
            w2[2] = splat2(bA.z); w2[3] = splat2(bA.w);
            w2[4] = splat2(bB.x); w2[5] = splat2(bB.y);
            w2[6] = splat2(bB.z); w2[7] = splat2(bB.w);
#pragma unroll
            for (int i = 0; i < 4; i++)
#pragma unroll
                for (int j = 0; j < 8; j++)
                    fma2(acc2[i][j], a2[i], w2[j]);
        }

        if (more) {
            As[nxt][kqA0*4+0][lrA0] = av0.x; As[nxt][kqA0*4+1][lrA0] = av0.y;
            As[nxt][kqA0*4+2][lrA0] = av0.z; As[nxt][kqA0*4+3][lrA0] = av0.w;
            As[nxt][kqA1*4+0][lrA1] = av1.x; As[nxt][kqA1*4+1][lrA1] = av1.y;
            As[nxt][kqA1*4+2][lrA1] = av1.z; As[nxt][kqA1*4+3][lrA1] = av1.w;
            Ws[nxt][kqA0*4+0][lrA0] = wv0.x; Ws[nxt][kqA0*4+1][lrA0] = wv0.y;
            Ws[nxt][kqA0*4+2][lrA0] = wv0.z; Ws[nxt][kqA0*4+3][lrA0] = wv0.w;
            Ws[nxt][kqA1*4+0][lrA1] = wv1.x; Ws[nxt][kqA1*4+1][lrA1] = wv1.y;
            Ws[nxt][kqA1*4+2][lrA1] = wv1.z; Ws[nxt][kqA1*4+3][lrA1] = wv1.w;
            __syncthreads();
        }
    }

    float biasA[4], biasB[4];
#pragma unroll
    for (int j = 0; j < 4; j++) {
        int na = bn + col0a + j, nb = bn + col0b + j;
        biasA[j] = ba[na] + (bb ? bb[na] : 0.f);
        biasB[j] = ba[nb] + (bb ? bb[nb] : 0.f);
    }
#pragma unroll
    for (int i = 0; i < 4; i++) {
        long mA = bm + row0 + 2 * i;
        long mB = mA + 1;
        float2 u[8];
#pragma unroll
        for (int j = 0; j < 8; j++) u[j] = unpack2(acc2[i][j]);
        float4 oA0 = {u[0].x + biasA[0], u[1].x + biasA[1], u[2].x + biasA[2], u[3].x + biasA[3]};
        float4 oA1 = {u[4].x + biasB[0], u[5].x + biasB[1], u[6].x + biasB[2], u[7].x + biasB[3]};
        float4 oB0 = {u[0].y + biasA[0], u[1].y + biasA[1], u[2].y + biasA[2], u[3].y + biasA[3]};
        float4 oB1 = {u[4].y + biasB[0], u[5].y + biasB[1], u[6].y + biasB[2], u[7].y + biasB[3]};
        *(float4*)&C[mA * N + bn + col0a] = oA0;
        *(float4*)&C[mA * N + bn + col0b] = oA1;
        *(float4*)&C[mB * N + bn + col0a] = oB0;
        *(float4*)&C[mB * N + bn + col0b] = oB1;
    }
}

// ---------------------------------------------------------------
// Persistent LSTM layer kernel v2: 128 blocks x 512 THREADS (16 warps,
// 4/SMSP), 2x2 micro-tile/thread. W_hh (32x1024) in XOR-swizzled smem.
// h staged via DOUBLE-BUFFERED smem chunks (1 syncthreads per chunk).
// smem: W 128K + 2xHs 67.6K + Pm 8.4K + Cs 2K = 209,152 B
// ---------------------------------------------------------------
__global__ __launch_bounds__(512, 1)
void lstm_layer_kernel(const float* __restrict__ xg,    // [S][64][4096]
                       const float* __restrict__ Whh,   // [4096][1024]
                       float* __restrict__ h,           // [2][64][1024]
                       float* __restrict__ y,           // [B][S][H]
                       float* __restrict__ out_h,
                       float* __restrict__ out_c)
{
    extern __shared__ float smem[];
    float* Wall = smem;                          // 32*1024 floats, swizzled
    float* HsF  = smem + 32 * 1024;              // 2 buffers x 64 rows x 33 f4
    float* Pm   = HsF + 2 * 64 * 132;            // 64*33
    float* Cs   = Pm + 64 * 33;                  // 512

    float4*     Hs4 = (float4*)HsF;
    ulonglong2* HsU = (ulonglong2*)HsF;
    const int   HBUF = 64 * 33;                  // float4 / u2 units per buffer

    const int tid = threadIdx.x;
    const int j0  = blockIdx.x * 8;
    const int tx  = tid & 15;
    const int ty  = tid >> 4;                    // 0..31
    const int c0  = tx * 2;
    const int r0  = ty * 2;                      // 2 batch rows per thread
    const int swz = tx & 7;

    // staging map: chunk = 64 rows x 32 float4 = 2048 f4; 4 per thread
    int soff[4];   // gmem float offset (row*HH + kc*4); chunk adds cc*128
    int sslot[4];  // smem float4 slot within buffer (row*33 + kc)
#pragma unroll
    for (int i = 0; i < 4; i++) {
        int idx = i * 512 + tid;
        int row = idx >> 5, kc = idx & 31;
        soff[i]  = row * HH + kc * 4;
        sslot[i] = row * 33 + kc;
    }

    // ---- prologue: zero h (both buffers), Cs; load swizzled W tile ----
    {
        float2 z2 = make_float2(0.f, 0.f);
        *(float2*)&h[blockIdx.x * 1024 + tid * 2] = z2;   // 128*1024 = 2*BH
        Cs[tid] = 0.f;
    }
#pragma unroll 4
    for (int i = 0; i < 16; i++) {
        int idx = i * 512 + tid;
        int wr = idx >> 8;
        int kq = idx & 255;
        int grow = (wr >> 3) * HH + j0 + (wr & 7);
        float4 v = *(const float4*)(Whh + (long)grow * HH + kq * 4);
        int slot = kq ^ ((wr >> 1) & 7);
        *(float4*)&Wall[wr * 1024 + slot * 4] = v;
    }

    unsigned nbar = 0;
    __syncthreads();
    nbar++;
    if (tid == 0) {
        __threadfence();
        atomicAdd(&g_bar, 1u);
        while (*(volatile unsigned*)&g_bar < nbar * NBLK) { }
    }
    __syncthreads();

    const ulonglong2* Wp0 = (const ulonglong2*)&Wall[c0 * 1024];
    const ulonglong2* Wp1 = (const ulonglong2*)&Wall[(c0 + 1) * 1024];

    for (int t = 0; t < SS; t++) {
        const float* h_in  = h + (size_t)(t & 1) * BH;
        float*       h_out = h + (size_t)((t + 1) & 1) * BH;
        const float* xg_t  = xg + (size_t)t * BB * G4;

        // xg contribution for this thread's 2x2 micro-tile
        const int gate = c0 >> 3;
        const int jl0  = c0 & 7;
        float2 xv[2];
#pragma unroll
        for (int r = 0; r < 2; r++)
            xv[r] = *(const float2*)(xg_t + (long)(r0 + r) * G4 + gate * HH + j0 + jl0);

        u64 acc[2][2];
        acc[0][0] = acc[0][1] = acc[1][0] = acc[1][1] = 0ull;

        // prefetch chunk 0
        float4 pf[4];
#pragma unroll
        for (int i = 0; i < 4; i++)
            pf[i] = __ldcg((const float4*)(h_in + soff[i]));

#pragma unroll 1
        for (int cc = 0; cc < 8; cc++) {
            const int bufo = (cc & 1) * HBUF;
#pragma unroll
            for (int i = 0; i < 4; i++) Hs4[bufo + sslot[i]] = pf[i];
            __syncthreads();
            if (cc < 7) {
#pragma unroll
                for (int i = 0; i < 4; i++)
                    pf[i] = __ldcg((const float4*)(h_in + soff[i] + (cc + 1) * 128));
            }

            const int kqb = cc * 32;
            const ulonglong2* Hr0 = HsU + bufo + (r0    ) * 33;
            const ulonglong2* Hr1 = HsU + bufo + (r0 + 1) * 33;
#pragma unroll 4
            for (int kql = 0; kql < 32; kql++) {
                int s = (kqb + kql) ^ swz;
                ulonglong2 w0 = Wp0[s];
                ulonglong2 w1 = Wp1[s];
                ulonglong2 h0 = Hr0[kql];
                ulonglong2 h1 = Hr1[kql];
                fma2(acc[0][0], h0.x, w0.x); fma2(acc[0][0], h0.y, w0.y);
                fma2(acc[0][1], h0.x, w1.x); fma2(acc[0][1], h0.y, w1.y);
                fma2(acc[1][0], h1.x, w0.x); fma2(acc[1][0], h1.y, w0.y);
                fma2(acc[1][1], h1.x, w1.x); fma2(acc[1][1], h1.y, w1.y);
            }
        }

        // fold lo+hi, add xg, stash pre-activations
#pragma unroll
        for (int r = 0; r < 2; r++) {
            int b = r0 + r;
            float2 u0 = unpack2(acc[r][0]);
            float2 u1 = unpack2(acc[r][1]);
            Pm[b * 33 + c0]     = u0.x + u0.y + xv[r].x;
            Pm[b * 33 + c0 + 1] = u1.x + u1.y + xv[r].y;
        }
        __syncthreads();

        // gate math: 512 (b, jl) pairs, 1 per thread
        {
            int b  = tid >> 3;
            int jl = tid & 7;
            int j  = j0 + jl;
            float iv = fast_sig (Pm[b * 33 + 0  + jl]);
            float fv = fast_sig (Pm[b * 33 + 8  + jl]);
            float gv = fast_tanh(Pm[b * 33 + 16 + jl]);
            float ov = fast_sig (Pm[b * 33 + 24 + jl]);
            float cn = fv * Cs[tid] + iv * gv;
            Cs[tid] = cn;
            float hn = ov * fast_tanh(cn);
            __stcg(h_out + (long)b * HH + j, hn);
            y[((long)b * SS + t) * HH + j] = hn;
            if (t == SS - 1) {
                out_h[(long)b * HH + j] = hn;
                out_c[(long)b * HH + j] = cn;
            }
        }

        // grid barrier: everyone's h_out visible before next step reads it
        __threadfence();
        __syncthreads();
        nbar++;
        if (tid == 0) {
            atomicAdd(&g_bar, 1u);
            while (*(volatile unsigned*)&g_bar < nbar * NBLK) { }
            __threadfence();
        }
        __syncthreads();
    }
}

extern "C" void kernel_launch(void* const* d_in, const int* in_sizes, int n_in,
                              void* d_out, int out_size)
{
    const float* x     = (const float*)d_in[0];
    const float* W_ih0 = (const float*)d_in[1];
    const float* W_hh0 = (const float*)d_in[2];
    const float* b_ih0 = (const float*)d_in[3];
    const float* b_hh0 = (const float*)d_in[4];
    const float* W_ih1 = (const float*)d_in[5];
    const float* W_hh1 = (const float*)d_in[6];
    const float* b_ih1 = (const float*)d_in[7];
    const float* b_hh1 = (const float*)d_in[8];
    const float* W_fc  = (const float*)d_in[9];
    const float* b_fc  = (const float*)d_in[10];
    float* out = (float*)d_out;

    float *xg, *y, *h;
    unsigned* bar;
    cudaGetSymbolAddress((void**)&xg,  g_xg);
    cudaGetSymbolAddress((void**)&y,   g_y);
    cudaGetSymbolAddress((void**)&h,   g_h);
    cudaGetSymbolAddress((void**)&bar, g_bar);

    const int SMEM_LAYER = (32 * 1024 + 2 * 64 * 132 + 64 * 33 + 512) * 4;  // 209,152
    cudaFuncSetAttribute(lstm_layer_kernel,
                         cudaFuncAttributeMaxDynamicSharedMemorySize, SMEM_LAYER);

    const int M = SS * BB;  // 32768

    // shift ncu's capture window (-s 5 -c 1) -> launch #6 = layer-0 LSTM
    noop_kernel<<<1, 32>>>();
    noop_kernel<<<1, 32>>>();
    noop_kernel<<<1, 32>>>();
    noop_kernel<<<1, 32>>>();

    // ---------------- layer 0 ----------------
    gemm_kernel<<<dim3(G4 / 128, M / 128), 256>>>(
        x, W_ih0, b_ih0, b_hh0, xg, M, G4, II, 1);
    cudaMemsetAsync(bar, 0, sizeof(unsigned));
    lstm_layer_kernel<<<NBLK, 512, SMEM_LAYER>>>(
        xg, W_hh0, h, y,
        out + OUT_ELEMS,
        out + OUT_ELEMS + 2 * BH);

    // ---------------- layer 1 ----------------
    gemm_kernel<<<dim3(G4 / 128, M / 128), 256>>>(
        y, W_ih1, b_ih1, b_hh1, xg, M, G4, HH, 1);
    cudaMemsetAsync(bar, 0, sizeof(unsigned));
    lstm_layer_kernel<<<NBLK, 512, SMEM_LAYER>>>(
        xg, W_hh1, h, y,
        out + OUT_ELEMS + BH,
        out + OUT_ELEMS + 3 * BH);

    // ---------------- FC ----------------
    gemm_kernel<<<dim3(OO / 128, M / 128), 256>>>(
        y, W_fc, b_fc, nullptr, out, M, OO, HH, 0);
}

// round 12
// speedup vs baseline: 1.3207x; 1.3207x over previous
#include <cuda_runtime.h>
#include <math.h>
#include <stdint.h>

#define BB   64
#define SS   512
#define II   512
#define HH   1024
#define G4   4096
#define OO   512
#define BH   (BB*HH)          // 65536
#define OUT_ELEMS (BB*SS*OO)  // 16777216
#define NBLK 128

typedef unsigned long long u64;

// -------- scratch (device globals; allocation-free per rules) --------
__device__ float g_xg[(size_t)SS * BB * G4];   // 512 MB, reused for both layers
__device__ float g_y [(size_t)BB * SS * HH];   // 128 MB, y0 then y1 (in place)
__device__ float g_h [2 * BH + 64];            // double-buffered hidden state
__device__ unsigned g_bar;                     // grid barrier counter

// ---------------- f32x2 helpers (sm_103a packed fp32 pipe) ----------------
__device__ __forceinline__ void fma2(u64& d, u64 a, u64 b) {
    asm("fma.rn.f32x2 %0, %1, %2, %3;" : "=l"(d) : "l"(a), "l"(b), "l"(d));
}
__device__ __forceinline__ float2 unpack2(u64 a) {
    float2 r; asm("mov.b64 {%0, %1}, %2;" : "=f"(r.x), "=f"(r.y) : "l"(a)); return r;
}
__device__ __forceinline__ float fast_sig(float x) {
    return __fdividef(1.f, 1.f + __expf(-x));
}
__device__ __forceinline__ float fast_tanh(float x) {
    return 2.f * fast_sig(2.f * x) - 1.f;
}

// ---------------- 3xTF32 helpers ----------------
// hi = x truncated to tf32 mantissa (exact tf32); lo = x - hi (exact fp32)
__device__ __forceinline__ void tf32_split(float x, float& h, float& l) {
    h = __uint_as_float(__float_as_uint(x) & 0xFFFFE000u);
    l = x - h;
}
__device__ __forceinline__ void mma_tf32(float& c0, float& c1, float& c2, float& c3,
                                         uint32_t a0, uint32_t a1, uint32_t a2, uint32_t a3,
                                         uint32_t b0, uint32_t b1) {
    asm volatile(
        "mma.sync.aligned.m16n8k8.row.col.f32.tf32.tf32.f32 "
        "{%0,%1,%2,%3}, {%4,%5,%6,%7}, {%8,%9}, {%0,%1,%2,%3};"
        : "+f"(c0), "+f"(c1), "+f"(c2), "+f"(c3)
        : "r"(a0), "r"(a1), "r"(a2), "r"(a3), "r"(b0), "r"(b1));
}

// =================================================================
// 3xTF32 tensor-core GEMM: C[m][n] = sum_k A[map(m)][k]*W[n][k] + bias
// CTA 128x128, K chunks of 32 floats, double-buffered smem, 8 warps,
// warp tile m64n32 (4x4 m16n8k8 atoms, 3 MMAs each for hi/lo split).
// Smem per stage (floats): Ahi[4096] Alo[4096] Whi[4096] Wlo[4096].
// Swizzle: f4 slot(row,kq) = row*8 + (kq ^ (row&7))  -> STS.128 and
// fragment LDS both conflict-free.
// =================================================================
#define KC 32
#define STG_F 16384        // floats per stage
#define OFF_ALO 4096
#define OFF_WHI 8192
#define OFF_WLO 12288

__global__ __launch_bounds__(256, 1)
void gemm_tc_kernel(const float* __restrict__ A, const float* __restrict__ W,
                    const float* __restrict__ ba, const float* __restrict__ bb,
                    float* __restrict__ C, int M, int N, int K, int mapA)
{
    extern __shared__ __align__(16) float smem[];   // 2 * STG_F floats

    const int tid = threadIdx.x;
    const int wid = tid >> 5;
    const int lid = tid & 31;
    const int bn  = blockIdx.x * 128;
    const int bm  = blockIdx.y * 128;

    const int warp_m = wid >> 2;       // 0..1
    const int warp_n = wid & 3;        // 0..3
    const int m0w = warp_m * 64;
    const int n0w = warp_n * 32;
    const int g   = lid >> 2;          // 0..7
    const int tig = lid & 3;           // 0..3

    // ---- loader maps: idx = j*256+tid; row = idx>>3 (0..127), kq = idx&7 ----
    const float* aptr[4]; const float* wptr[4];
    int asl[4], wsl[4];                 // float offsets in smem
#pragma unroll
    for (int j = 0; j < 4; j++) {
        int idx = j * 256 + tid;
        int row = idx >> 3, kq = idx & 7;
        int m = bm + row;
        long ar = mapA ? ((long)(m & 63) * SS + (m >> 6)) : (long)m;
        aptr[j] = A + ar * K + kq * 4;
        wptr[j] = W + (long)(bn + row) * K + kq * 4;
        int slot = (row * 8 + (kq ^ (row & 7))) * 4;
        asl[j] = slot; wsl[j] = slot;
    }

    float c[4][4][4];
#pragma unroll
    for (int i = 0; i < 4; i++)
#pragma unroll
        for (int j = 0; j < 4; j++)
#pragma unroll
            for (int r = 0; r < 4; r++) c[i][j][r] = 0.f;

    const int nc = K / KC;

    // ---- prologue: stage chunk 0 ----
    {
        float* sb = smem;
#pragma unroll
        for (int j = 0; j < 4; j++) {
            float4 v = __ldg((const float4*)aptr[j]);
            float4 h, l;
            tf32_split(v.x, h.x, l.x); tf32_split(v.y, h.y, l.y);
            tf32_split(v.z, h.z, l.z); tf32_split(v.w, h.w, l.w);
            *(float4*)&sb[asl[j]]           = h;
            *(float4*)&sb[OFF_ALO + asl[j]] = l;
            float4 w = __ldg((const float4*)wptr[j]);
            tf32_split(w.x, h.x, l.x); tf32_split(w.y, h.y, l.y);
            tf32_split(w.z, h.z, l.z); tf32_split(w.w, h.w, l.w);
            *(float4*)&sb[OFF_WHI + wsl[j]] = h;
            *(float4*)&sb[OFF_WLO + wsl[j]] = l;
        }
    }
    __syncthreads();

    for (int cc = 0; cc < nc; cc++) {
        const bool more = (cc + 1) < nc;

        // prefetch next chunk's globals into registers
        float4 pa[4], pw[4];
        if (more) {
            int ko = (cc + 1) * KC;
#pragma unroll
            for (int j = 0; j < 4; j++) {
                pa[j] = __ldg((const float4*)(aptr[j] + ko));
                pw[j] = __ldg((const float4*)(wptr[j] + ko));
            }
        }

        // ---- MMA phase on current buffer ----
        const float*   sb = smem + (cc & 1) * STG_F;
        const uint32_t* Ah = (const uint32_t*)sb;
        const uint32_t* Al = (const uint32_t*)(sb + OFF_ALO);
        const uint32_t* Wh = (const uint32_t*)(sb + OFF_WHI);
        const uint32_t* Wl = (const uint32_t*)(sb + OFF_WLO);

#pragma unroll
        for (int s = 0; s < 4; s++) {
            const int slotE = (((2 * s)     ^ g) * 4) + tig;
            const int slotO = (((2 * s + 1) ^ g) * 4) + tig;

            uint32_t ah[4][4], al[4][4];
#pragma unroll
            for (int i = 0; i < 4; i++) {
                int base = (m0w + 16 * i + g) * 32;
                ah[i][0] = Ah[base + slotE];        al[i][0] = Al[base + slotE];
                ah[i][1] = Ah[base + 256 + slotE];  al[i][1] = Al[base + 256 + slotE];
                ah[i][2] = Ah[base + slotO];        al[i][2] = Al[base + slotO];
                ah[i][3] = Ah[base + 256 + slotO];  al[i][3] = Al[base + 256 + slotO];
            }
            uint32_t bh[4][2], bl[4][2];
#pragma unroll
            for (int j = 0; j < 4; j++) {
                int base = (n0w + 8 * j + g) * 32;
                bh[j][0] = Wh[base + slotE];  bl[j][0] = Wl[base + slotE];
                bh[j][1] = Wh[base + slotO];  bl[j][1] = Wl[base + slotO];
            }
#pragma unroll
            for (int i = 0; i < 4; i++)
#pragma unroll
                for (int j = 0; j < 4; j++) {
                    mma_tf32(c[i][j][0], c[i][j][1], c[i][j][2], c[i][j][3],
                             ah[i][0], ah[i][1], ah[i][2], ah[i][3],
                             bh[j][0], bh[j][1]);
                    mma_tf32(c[i][j][0], c[i][j][1], c[i][j][2], c[i][j][3],
                             ah[i][0], ah[i][1], ah[i][2], ah[i][3],
                             bl[j][0], bl[j][1]);
                    mma_tf32(c[i][j][0], c[i][j][1], c[i][j][2], c[i][j][3],
                             al[i][0], al[i][1], al[i][2], al[i][3],
                             bh[j][0], bh[j][1]);
                }
        }

        // ---- stage next chunk ----
        if (more) {
            float* nb = smem + ((cc + 1) & 1) * STG_F;
#pragma unroll
            for (int j = 0; j < 4; j++) {
                float4 h, l;
                tf32_split(pa[j].x, h.x, l.x); tf32_split(pa[j].y, h.y, l.y);
                tf32_split(pa[j].z, h.z, l.z); tf32_split(pa[j].w, h.w, l.w);
                *(float4*)&nb[asl[j]]           = h;
                *(float4*)&nb[OFF_ALO + asl[j]] = l;
                tf32_split(pw[j].x, h.x, l.x); tf32_split(pw[j].y, h.y, l.y);
                tf32_split(pw[j].z, h.z, l.z); tf32_split(pw[j].w, h.w, l.w);
                *(float4*)&nb[OFF_WHI + wsl[j]] = h;
                *(float4*)&nb[OFF_WLO + wsl[j]] = l;
            }
            __syncthreads();
        }
    }

    // ---- epilogue: bias + store ----
#pragma unroll
    for (int j = 0; j < 4; j++) {
        int n = bn + n0w + 8 * j + 2 * tig;
        float2 bv = *(const float2*)&ba[n];
        if (bb) {
            float2 b2 = *(const float2*)&bb[n];
            bv.x += b2.x; bv.y += b2.y;
        }
#pragma unroll
        for (int i = 0; i < 4; i++) {
            long m0 = bm + m0w + 16 * i + g;
            long m1 = m0 + 8;
            float2 o0 = {c[i][j][0] + bv.x, c[i][j][1] + bv.y};
            float2 o1 = {c[i][j][2] + bv.x, c[i][j][3] + bv.y};
            *(float2*)&C[m0 * N + n] = o0;
            *(float2*)&C[m1 * N + n] = o1;
        }
    }
}

// ---------------------------------------------------------------
// Persistent LSTM layer kernel (round-7 best configuration, unchanged).
// ---------------------------------------------------------------
__global__ __launch_bounds__(256, 1)
void lstm_layer_kernel(const float* __restrict__ xg,    // [S][64][4096]
                       const float* __restrict__ Whh,   // [4096][1024]
                       float* __restrict__ h,           // [2][64][1024]
                       float* __restrict__ y,           // [B][S][H]
                       float* __restrict__ out_h,
                       float* __restrict__ out_c)
{
    extern __shared__ float lsm[];
    float* Wall = lsm;                           // 32*1024 floats, swizzled
    float* HsF  = lsm + 32 * 1024;               // 64 rows * 33 float4
    float* Pm   = HsF + 64 * 132;                // 64*33
    float* Cs   = Pm + 64 * 33;                  // 512

    float4*     Hs4 = (float4*)HsF;
    ulonglong2* HsU = (ulonglong2*)HsF;

    const int tid = threadIdx.x;
    const int j0  = blockIdx.x * 8;
    const int tx  = tid & 15;
    const int ty  = tid >> 4;
    const int c0  = tx * 2;
    const int r0  = ty * 4;
    const int swz = tx & 7;

    int soff[8];
    int sslot[8];
#pragma unroll
    for (int i = 0; i < 8; i++) {
        int idx = i * 256 + tid;
        int row = idx >> 5, kc = idx & 31;
        soff[i]  = row * HH + kc * 4;
        sslot[i] = row * 33 + kc;
    }

    {
        float4 z = make_float4(0.f, 0.f, 0.f, 0.f);
        *(float4*)&h[blockIdx.x * 1024 + tid * 4] = z;
        Cs[tid]       = 0.f;
        Cs[tid + 256] = 0.f;
    }
#pragma unroll 4
    for (int i = 0; i < 32; i++) {
        int idx = i * 256 + tid;
        int wr = idx >> 8;
        int kq = idx & 255;
        int grow = (wr >> 3) * HH + j0 + (wr & 7);
        float4 v = *(const float4*)(Whh + (long)grow * HH + kq * 4);
        int slot = kq ^ ((wr >> 1) & 7);
        *(float4*)&Wall[wr * 1024 + slot * 4] = v;
    }

    unsigned nbar = 0;
    __syncthreads();
    nbar++;
    if (tid == 0) {
        __threadfence();
        atomicAdd(&g_bar, 1u);
        while (*(volatile unsigned*)&g_bar < nbar * NBLK) { }
    }
    __syncthreads();

    const ulonglong2* Wp0 = (const ulonglong2*)&Wall[c0 * 1024];
    const ulonglong2* Wp1 = (const ulonglong2*)&Wall[(c0 + 1) * 1024];

    for (int t = 0; t < SS; t++) {
        const float* h_in  = h + (size_t)(t & 1) * BH;
        float*       h_out = h + (size_t)((t + 1) & 1) * BH;
        const float* xg_t  = xg + (size_t)t * BB * G4;

        const int gate = c0 >> 3;
        const int jl0  = c0 & 7;
        float2 xv[4];
#pragma unroll
        for (int r = 0; r < 4; r++)
            xv[r] = *(const float2*)(xg_t + (long)(r0 + r) * G4 + gate * HH + j0 + jl0);

        u64 acc[4][2];
#pragma unroll
        for (int r = 0; r < 4; r++) { acc[r][0] = 0ull; acc[r][1] = 0ull; }

        float4 pf[8];
#pragma unroll
        for (int i = 0; i < 8; i++)
            pf[i] = __ldcg((const float4*)(h_in + soff[i]));

#pragma unroll 1
        for (int cc = 0; cc < 8; cc++) {
            __syncthreads();
#pragma unroll
            for (int i = 0; i < 8; i++) Hs4[sslot[i]] = pf[i];
            __syncthreads();
            if (cc < 7) {
#pragma unroll
                for (int i = 0; i < 8; i++)
                    pf[i] = __ldcg((const float4*)(h_in + soff[i] + (cc + 1) * 128));
            }

            const int kqb = cc * 32;
#pragma unroll 4
            for (int kql = 0; kql < 32; kql++) {
                int s = (kqb + kql) ^ swz;
                ulonglong2 w0 = Wp0[s];
                ulonglong2 w1 = Wp1[s];
#pragma unroll
                for (int r = 0; r < 4; r++) {
                    ulonglong2 hv = HsU[(r0 + r) * 33 + kql];
                    fma2(acc[r][0], hv.x, w0.x);
                    fma2(acc[r][0], hv.y, w0.y);
                    fma2(acc[r][1], hv.x, w1.x);
                    fma2(acc[r][1], hv.y, w1.y);
                }
            }
        }

#pragma unroll
        for (int r = 0; r < 4; r++) {
            int b = r0 + r;
            float2 u0 = unpack2(acc[r][0]);
            float2 u1 = unpack2(acc[r][1]);
            Pm[b * 33 + c0]     = u0.x + u0.y + xv[r].x;
            Pm[b * 33 + c0 + 1] = u1.x + u1.y + xv[r].y;
        }
        __syncthreads();

#pragma unroll
        for (int pi = 0; pi < 2; pi++) {
            int p  = tid + pi * 256;
            int b  = p >> 3;
            int jl = p & 7;
            int j  = j0 + jl;
            float iv = fast_sig (Pm[b * 33 + 0  + jl]);
            float fv = fast_sig (Pm[b * 33 + 8  + jl]);
            float gv = fast_tanh(Pm[b * 33 + 16 + jl]);
            float ov = fast_sig (Pm[b * 33 + 24 + jl]);
            float cn = fv * Cs[b * 8 + jl] + iv * gv;
            Cs[b * 8 + jl] = cn;
            float hn = ov * fast_tanh(cn);
            __stcg(h_out + (long)b * HH + j, hn);
            y[((long)b * SS + t) * HH + j] = hn;
            if (t == SS - 1) {
                out_h[(long)b * HH + j] = hn;
                out_c[(long)b * HH + j] = cn;
            }
        }

        __threadfence();
        __syncthreads();
        nbar++;
        if (tid == 0) {
            atomicAdd(&g_bar, 1u);
            while (*(volatile unsigned*)&g_bar < nbar * NBLK) { }
            __threadfence();
        }
        __syncthreads();
    }
}

extern "C" void kernel_launch(void* const* d_in, const int* in_sizes, int n_in,
                              void* d_out, int out_size)
{
    const float* x     = (const float*)d_in[0];
    const float* W_ih0 = (const float*)d_in[1];
    const float* W_hh0 = (const float*)d_in[2];
    const float* b_ih0 = (const float*)d_in[3];
    const float* b_hh0 = (const float*)d_in[4];
    const float* W_ih1 = (const float*)d_in[5];
    const float* W_hh1 = (const float*)d_in[6];
    const float* b_ih1 = (const float*)d_in[7];
    const float* b_hh1 = (const float*)d_in[8];
    const float* W_fc  = (const float*)d_in[9];
    const float* b_fc  = (const float*)d_in[10];
    float* out = (float*)d_out;

    float *xg, *y, *h;
    unsigned* bar;
    cudaGetSymbolAddress((void**)&xg,  g_xg);
    cudaGetSymbolAddress((void**)&y,   g_y);
    cudaGetSymbolAddress((void**)&h,   g_h);
    cudaGetSymbolAddress((void**)&bar, g_bar);

    const int SMEM_LAYER = (32 * 1024 + 64 * 132 + 64 * 33 + 512) * 4;  // 175,360
    cudaFuncSetAttribute(lstm_layer_kernel,
                         cudaFuncAttributeMaxDynamicSharedMemorySize, SMEM_LAYER);
    const int SMEM_TC = 2 * STG_F * 4;                                  // 131,072
    cudaFuncSetAttribute(gemm_tc_kernel,
                         cudaFuncAttributeMaxDynamicSharedMemorySize, SMEM_TC);

    const int M = SS * BB;  // 32768

    // ---------------- layer 0 ----------------
    gemm_tc_kernel<<<dim3(G4 / 128, M / 128), 256, SMEM_TC>>>(
        x, W_ih0, b_ih0, b_hh0, xg, M, G4, II, 1);
    cudaMemsetAsync(bar, 0, sizeof(unsigned));
    lstm_layer_kernel<<<NBLK, 256, SMEM_LAYER>>>(
        xg, W_hh0, h, y,
        out + OUT_ELEMS,
        out + OUT_ELEMS + 2 * BH);

    // ---------------- layer 1 ----------------
    gemm_tc_kernel<<<dim3(G4 / 128, M / 128), 256, SMEM_TC>>>(
        y, W_ih1, b_ih1, b_hh1, xg, M, G4, HH, 1);
    cudaMemsetAsync(bar, 0, sizeof(unsigned));
    lstm_layer_kernel<<<NBLK, 256, SMEM_LAYER>>>(
        xg, W_hh1, h, y,
        out + OUT_ELEMS + BH,
        out + OUT_ELEMS + 3 * BH);

    // ---------------- FC ----------------
    gemm_tc_kernel<<<dim3(OO / 128, M / 128), 256, SMEM_TC>>>(
        y, W_fc, b_fc, nullptr, out, M, OO, HH, 0);
}

// round 13
// speedup vs baseline: 1.4289x; 1.0820x over previous
#include <cuda_runtime.h>
#include <cuda_bf16.h>
#include <math.h>
#include <stdint.h>

#define BB   64
#define SS   512
#define II   512
#define HH   1024
#define G4   4096
#define OO   512
#define BH   (BB*HH)          // 65536
#define OUT_ELEMS (BB*SS*OO)  // 16777216
#define NBLK 128

typedef unsigned long long u64;

// -------- scratch (device globals; allocation-free per rules) --------
__device__ float g_xg[(size_t)SS * BB * G4];   // 512 MB, reused for both layers
__device__ float g_y [(size_t)BB * SS * HH];   // 128 MB, y0 then y1 (in place)
__device__ float g_h [2 * BH + 64];            // double-buffered hidden state
__device__ unsigned g_bar;                     // grid barrier counter

// ---------------- f32x2 helpers (sm_103a packed fp32 pipe) ----------------
__device__ __forceinline__ void fma2(u64& d, u64 a, u64 b) {
    asm("fma.rn.f32x2 %0, %1, %2, %3;" : "=l"(d) : "l"(a), "l"(b), "l"(d));
}
__device__ __forceinline__ float2 unpack2(u64 a) {
    float2 r; asm("mov.b64 {%0, %1}, %2;" : "=f"(r.x), "=f"(r.y) : "l"(a)); return r;
}
__device__ __forceinline__ float fast_sig(float x) {
    return __fdividef(1.f, 1.f + __expf(-x));
}
__device__ __forceinline__ float fast_tanh(float x) {
    return 2.f * fast_sig(2.f * x) - 1.f;
}

// ---------------- bf16 split helpers ----------------
__device__ __forceinline__ uint32_t pack_bf16(float x, float y) {
    __nv_bfloat162 t = __floats2bfloat162_rn(x, y);
    return *(uint32_t*)&t;
}
// split float4 -> hi (2 words bf16x2) and mid (2 words)
__device__ __forceinline__ void split4(float4 v, uint2& hi, uint2& mid) {
    __nv_bfloat162 h01 = __floats2bfloat162_rn(v.x, v.y);
    __nv_bfloat162 h23 = __floats2bfloat162_rn(v.z, v.w);
    float2 f01 = __bfloat1622float2(h01);
    float2 f23 = __bfloat1622float2(h23);
    hi.x  = *(uint32_t*)&h01;
    hi.y  = *(uint32_t*)&h23;
    mid.x = pack_bf16(v.x - f01.x, v.y - f01.y);
    mid.y = pack_bf16(v.z - f23.x, v.w - f23.y);
}
__device__ __forceinline__ void mma_bf16(float& c0, float& c1, float& c2, float& c3,
                                         uint32_t a0, uint32_t a1, uint32_t a2, uint32_t a3,
                                         uint32_t b0, uint32_t b1) {
    asm volatile(
        "mma.sync.aligned.m16n8k16.row.col.f32.bf16.bf16.f32 "
        "{%0,%1,%2,%3}, {%4,%5,%6,%7}, {%8,%9}, {%0,%1,%2,%3};"
        : "+f"(c0), "+f"(c1), "+f"(c2), "+f"(c3)
        : "r"(a0), "r"(a1), "r"(a2), "r"(a3), "r"(b0), "r"(b1));
}

// =================================================================
// 3xBF16 tensor-core GEMM: C[m][n] = sum_k A[map(m)][k]*W[n][k] + bias
// CTA 128x128, K chunks of 32 floats, double-buffered smem, 8 warps,
// warp tile m64n32, m16n8k16 atoms, 3 MMAs per atom (hi/mid split).
// Smem per stage (uint32 words, bf16x2): Ahi[2048] Amid[2048]
// Whi[2048] Wmid[2048] = 32 KB; two stages = 64 KB.
// Swizzle: word slot(row, w) = row*16 + (w ^ ((row&7)<<1)).
// =================================================================
#define KC 32
#define STG_W  8192        // words per stage
#define OFF_AM 2048
#define OFF_WH 4096
#define OFF_WM 6144

__global__ __launch_bounds__(256, 1)
void gemm_tc_kernel(const float* __restrict__ A, const float* __restrict__ W,
                    const float* __restrict__ ba, const float* __restrict__ bb,
                    float* __restrict__ C, int M, int N, int K, int mapA)
{
    extern __shared__ __align__(16) uint32_t smw[];   // 2 * STG_W words

    const int tid = threadIdx.x;
    const int wid = tid >> 5;
    const int lid = tid & 31;
    const int bn  = blockIdx.x * 128;
    const int bm  = blockIdx.y * 128;

    const int warp_m = wid >> 2;       // 0..1
    const int warp_n = wid & 3;        // 0..3
    const int m0w = warp_m * 64;
    const int n0w = warp_n * 32;
    const int g   = lid >> 2;          // 0..7
    const int tig = lid & 3;           // 0..3
    const int xm  = g << 1;            // swizzle mask for fragment reads

    // ---- loader maps: idx = j*256+tid; row = idx>>3 (0..127), kq = idx&7 ----
    const float* aptr[4]; const float* wptr[4];
    int sl[4];                          // swizzled word offset (2 words)
#pragma unroll
    for (int j = 0; j < 4; j++) {
        int idx = j * 256 + tid;
        int row = idx >> 3, kq = idx & 7;
        int m = bm + row;
        long ar = mapA ? ((long)(m & 63) * SS + (m >> 6)) : (long)m;
        aptr[j] = A + ar * K + kq * 4;
        wptr[j] = W + (long)(bn + row) * K + kq * 4;
        sl[j] = row * 16 + ((2 * kq) ^ ((row & 7) << 1));
    }

    // fragment row bases (word units)
    int rA0[4], rA1[4], rB[4];
#pragma unroll
    for (int i = 0; i < 4; i++) {
        rA0[i] = (m0w + 16 * i + g) * 16;
        rA1[i] = rA0[i] + 128;             // +8 rows
        rB[i]  = (n0w + 8 * i + g) * 16;
    }

    float c[4][4][4];
#pragma unroll
    for (int i = 0; i < 4; i++)
#pragma unroll
        for (int j = 0; j < 4; j++)
#pragma unroll
            for (int r = 0; r < 4; r++) c[i][j][r] = 0.f;

    const int nc = K / KC;

    // ---- prologue: stage chunk 0 ----
    {
        uint32_t* sb = smw;
#pragma unroll
        for (int j = 0; j < 4; j++) {
            uint2 hi, mid;
            split4(__ldg((const float4*)aptr[j]), hi, mid);
            *(uint2*)&sb[sl[j]]          = hi;
            *(uint2*)&sb[OFF_AM + sl[j]] = mid;
            split4(__ldg((const float4*)wptr[j]), hi, mid);
            *(uint2*)&sb[OFF_WH + sl[j]] = hi;
            *(uint2*)&sb[OFF_WM + sl[j]] = mid;
        }
    }
    __syncthreads();

    for (int cc = 0; cc < nc; cc++) {
        const bool more = (cc + 1) < nc;

        // prefetch next chunk's globals into registers
        float4 pa[4], pw[4];
        if (more) {
            int ko = (cc + 1) * KC;
#pragma unroll
            for (int j = 0; j < 4; j++) {
                pa[j] = __ldg((const float4*)(aptr[j] + ko));
                pw[j] = __ldg((const float4*)(wptr[j] + ko));
            }
        }

        // ---- MMA phase on current buffer (2 k16 blocks) ----
        const uint32_t* sb = smw + (cc & 1) * STG_W;
#pragma unroll
        for (int blk = 0; blk < 2; blk++) {
            const int cbase = 8 * blk;
            const int w0 = (tig + cbase) ^ xm;
            const int w4 = (tig + 4 + cbase) ^ xm;

            uint32_t ah[4][4], am[4][4];
#pragma unroll
            for (int i = 0; i < 4; i++) {
                ah[i][0] = sb[rA0[i] + w0];  ah[i][1] = sb[rA1[i] + w0];
                ah[i][2] = sb[rA0[i] + w4];  ah[i][3] = sb[rA1[i] + w4];
                am[i][0] = sb[OFF_AM + rA0[i] + w0];  am[i][1] = sb[OFF_AM + rA1[i] + w0];
                am[i][2] = sb[OFF_AM + rA0[i] + w4];  am[i][3] = sb[OFF_AM + rA1[i] + w4];
            }
            uint32_t bh[4][2], bmf[4][2];
#pragma unroll
            for (int j = 0; j < 4; j++) {
                bh[j][0]  = sb[OFF_WH + rB[j] + w0];  bh[j][1]  = sb[OFF_WH + rB[j] + w4];
                bmf[j][0] = sb[OFF_WM + rB[j] + w0];  bmf[j][1] = sb[OFF_WM + rB[j] + w4];
            }
#pragma unroll
            for (int i = 0; i < 4; i++)
#pragma unroll
                for (int j = 0; j < 4; j++) {
                    mma_bf16(c[i][j][0], c[i][j][1], c[i][j][2], c[i][j][3],
                             ah[i][0], ah[i][1], ah[i][2], ah[i][3],
                             bh[j][0], bh[j][1]);
                    mma_bf16(c[i][j][0], c[i][j][1], c[i][j][2], c[i][j][3],
                             ah[i][0], ah[i][1], ah[i][2], ah[i][3],
                             bmf[j][0], bmf[j][1]);
                    mma_bf16(c[i][j][0], c[i][j][1], c[i][j][2], c[i][j][3],
                             am[i][0], am[i][1], am[i][2], am[i][3],
                             bh[j][0], bh[j][1]);
                }
        }

        // ---- stage next chunk ----
        if (more) {
            uint32_t* nb = smw + ((cc + 1) & 1) * STG_W;
#pragma unroll
            for (int j = 0; j < 4; j++) {
                uint2 hi, mid;
                split4(pa[j], hi, mid);
                *(uint2*)&nb[sl[j]]          = hi;
                *(uint2*)&nb[OFF_AM + sl[j]] = mid;
                split4(pw[j], hi, mid);
                *(uint2*)&nb[OFF_WH + sl[j]] = hi;
                *(uint2*)&nb[OFF_WM + sl[j]] = mid;
            }
            __syncthreads();
        }
    }

    // ---- epilogue: bias + store ----
#pragma unroll
    for (int j = 0; j < 4; j++) {
        int n = bn + n0w + 8 * j + 2 * tig;
        float2 bv = *(const float2*)&ba[n];
        if (bb) {
            float2 b2 = *(const float2*)&bb[n];
            bv.x += b2.x; bv.y += b2.y;
        }
#pragma unroll
        for (int i = 0; i < 4; i++) {
            long m0 = bm + m0w + 16 * i + g;
            long m1 = m0 + 8;
            float2 o0 = {c[i][j][0] + bv.x, c[i][j][1] + bv.y};
            float2 o1 = {c[i][j][2] + bv.x, c[i][j][3] + bv.y};
            *(float2*)&C[m0 * N + n] = o0;
            *(float2*)&C[m1 * N + n] = o1;
        }
    }
}

// ---------------------------------------------------------------
// Persistent LSTM layer kernel (round-7 best configuration, unchanged).
// ---------------------------------------------------------------
__global__ __launch_bounds__(256, 1)
void lstm_layer_kernel(const float* __restrict__ xg,    // [S][64][4096]
                       const float* __restrict__ Whh,   // [4096][1024]
                       float* __restrict__ h,           // [2][64][1024]
                       float* __restrict__ y,           // [B][S][H]
                       float* __restrict__ out_h,
                       float* __restrict__ out_c)
{
    extern __shared__ float lsm[];
    float* Wall = lsm;                           // 32*1024 floats, swizzled
    float* HsF  = lsm + 32 * 1024;               // 64 rows * 33 float4
    float* Pm   = HsF + 64 * 132;                // 64*33
    float* Cs   = Pm + 64 * 33;                  // 512

    float4*     Hs4 = (float4*)HsF;
    ulonglong2* HsU = (ulonglong2*)HsF;

    const int tid = threadIdx.x;
    const int j0  = blockIdx.x * 8;
    const int tx  = tid & 15;
    const int ty  = tid >> 4;
    const int c0  = tx * 2;
    const int r0  = ty * 4;
    const int swz = tx & 7;

    int soff[8];
    int sslot[8];
#pragma unroll
    for (int i = 0; i < 8; i++) {
        int idx = i * 256 + tid;
        int row = idx >> 5, kc = idx & 31;
        soff[i]  = row * HH + kc * 4;
        sslot[i] = row * 33 + kc;
    }

    {
        float4 z = make_float4(0.f, 0.f, 0.f, 0.f);
        *(float4*)&h[blockIdx.x * 1024 + tid * 4] = z;
        Cs[tid]       = 0.f;
        Cs[tid + 256] = 0.f;
    }
#pragma unroll 4
    for (int i = 0; i < 32; i++) {
        int idx = i * 256 + tid;
        int wr = idx >> 8;
        int kq = idx & 255;
        int grow = (wr >> 3) * HH + j0 + (wr & 7);
        float4 v = *(const float4*)(Whh + (long)grow * HH + kq * 4);
        int slot = kq ^ ((wr >> 1) & 7);
        *(float4*)&Wall[wr * 1024 + slot * 4] = v;
    }

    unsigned nbar = 0;
    __syncthreads();
    nbar++;
    if (tid == 0) {
        __threadfence();
        atomicAdd(&g_bar, 1u);
        while (*(volatile unsigned*)&g_bar < nbar * NBLK) { }
    }
    __syncthreads();

    const ulonglong2* Wp0 = (const ulonglong2*)&Wall[c0 * 1024];
    const ulonglong2* Wp1 = (const ulonglong2*)&Wall[(c0 + 1) * 1024];

    for (int t = 0; t < SS; t++) {
        const float* h_in  = h + (size_t)(t & 1) * BH;
        float*       h_out = h + (size_t)((t + 1) & 1) * BH;
        const float* xg_t  = xg + (size_t)t * BB * G4;

        const int gate = c0 >> 3;
        const int jl0  = c0 & 7;
        float2 xv[4];
#pragma unroll
        for (int r = 0; r < 4; r++)
            xv[r] = *(const float2*)(xg_t + (long)(r0 + r) * G4 + gate * HH + j0 + jl0);

        u64 acc[4][2];
#pragma unroll
        for (int r = 0; r < 4; r++) { acc[r][0] = 0ull; acc[r][1] = 0ull; }

        float4 pf[8];
#pragma unroll
        for (int i = 0; i < 8; i++)
            pf[i] = __ldcg((const float4*)(h_in + soff[i]));

#pragma unroll 1
        for (int cc = 0; cc < 8; cc++) {
            __syncthreads();
#pragma unroll
            for (int i = 0; i < 8; i++) Hs4[sslot[i]] = pf[i];
            __syncthreads();
            if (cc < 7) {
#pragma unroll
                for (int i = 0; i < 8; i++)
                    pf[i] = __ldcg((const float4*)(h_in + soff[i] + (cc + 1) * 128));
            }

            const int kqb = cc * 32;
#pragma unroll 4
            for (int kql = 0; kql < 32; kql++) {
                int s = (kqb + kql) ^ swz;
                ulonglong2 w0 = Wp0[s];
                ulonglong2 w1 = Wp1[s];
#pragma unroll
                for (int r = 0; r < 4; r++) {
                    ulonglong2 hv = HsU[(r0 + r) * 33 + kql];
                    fma2(acc[r][0], hv.x, w0.x);
                    fma2(acc[r][0], hv.y, w0.y);
                    fma2(acc[r][1], hv.x, w1.x);
                    fma2(acc[r][1], hv.y, w1.y);
                }
            }
        }

#pragma unroll
        for (int r = 0; r < 4; r++) {
            int b = r0 + r;
            float2 u0 = unpack2(acc[r][0]);
            float2 u1 = unpack2(acc[r][1]);
            Pm[b * 33 + c0]     = u0.x + u0.y + xv[r].x;
            Pm[b * 33 + c0 + 1] = u1.x + u1.y + xv[r].y;
        }
        __syncthreads();

#pragma unroll
        for (int pi = 0; pi < 2; pi++) {
            int p  = tid + pi * 256;
            int b  = p >> 3;
            int jl = p & 7;
            int j  = j0 + jl;
            float iv = fast_sig (Pm[b * 33 + 0  + jl]);
            float fv = fast_sig (Pm[b * 33 + 8  + jl]);
            float gv = fast_tanh(Pm[b * 33 + 16 + jl]);
            float ov = fast_sig (Pm[b * 33 + 24 + jl]);
            float cn = fv * Cs[b * 8 + jl] + iv * gv;
            Cs[b * 8 + jl] = cn;
            float hn = ov * fast_tanh(cn);
            __stcg(h_out + (long)b * HH + j, hn);
            y[((long)b * SS + t) * HH + j] = hn;
            if (t == SS - 1) {
                out_h[(long)b * HH + j] = hn;
                out_c[(long)b * HH + j] = cn;
            }
        }

        __threadfence();
        __syncthreads();
        nbar++;
        if (tid == 0) {
            atomicAdd(&g_bar, 1u);
            while (*(volatile unsigned*)&g_bar < nbar * NBLK) { }
            __threadfence();
        }
        __syncthreads();
    }
}

extern "C" void kernel_launch(void* const* d_in, const int* in_sizes, int n_in,
                              void* d_out, int out_size)
{
    const float* x     = (const float*)d_in[0];
    const float* W_ih0 = (const float*)d_in[1];
    const float* W_hh0 = (const float*)d_in[2];
    const float* b_ih0 = (const float*)d_in[3];
    const float* b_hh0 = (const float*)d_in[4];
    const float* W_ih1 = (const float*)d_in[5];
    const float* W_hh1 = (const float*)d_in[6];
    const float* b_ih1 = (const float*)d_in[7];
    const float* b_hh1 = (const float*)d_in[8];
    const float* W_fc  = (const float*)d_in[9];
    const float* b_fc  = (const float*)d_in[10];
    float* out = (float*)d_out;

    float *xg, *y, *h;
    unsigned* bar;
    cudaGetSymbolAddress((void**)&xg,  g_xg);
    cudaGetSymbolAddress((void**)&y,   g_y);
    cudaGetSymbolAddress((void**)&h,   g_h);
    cudaGetSymbolAddress((void**)&bar, g_bar);

    const int SMEM_LAYER = (32 * 1024 + 64 * 132 + 64 * 33 + 512) * 4;  // 175,360
    cudaFuncSetAttribute(lstm_layer_kernel,
                         cudaFuncAttributeMaxDynamicSharedMemorySize, SMEM_LAYER);
    const int SMEM_TC = 2 * STG_W * 4;                                  // 65,536
    cudaFuncSetAttribute(gemm_tc_kernel,
                         cudaFuncAttributeMaxDynamicSharedMemorySize, SMEM_TC);

    const int M = SS * BB;  // 32768

    // ---------------- layer 0 ----------------
    gemm_tc_kernel<<<dim3(G4 / 128, M / 128), 256, SMEM_TC>>>(
        x, W_ih0, b_ih0, b_hh0, xg, M, G4, II, 1);
    cudaMemsetAsync(bar, 0, sizeof(unsigned));
    lstm_layer_kernel<<<NBLK, 256, SMEM_LAYER>>>(
        xg, W_hh0, h, y,
        out + OUT_ELEMS,
        out + OUT_ELEMS + 2 * BH);

    // ---------------- layer 1 ----------------
    gemm_tc_kernel<<<dim3(G4 / 128, M / 128), 256, SMEM_TC>>>(
        y, W_ih1, b_ih1, b_hh1, xg, M, G4, HH, 1);
    cudaMemsetAsync(bar, 0, sizeof(unsigned));
    lstm_layer_kernel<<<NBLK, 256, SMEM_LAYER>>>(
        xg, W_hh1, h, y,
        out + OUT_ELEMS + BH,
        out + OUT_ELEMS + 3 * BH);

    // ---------------- FC ----------------
    gemm_tc_kernel<<<dim3(OO / 128, M / 128), 256, SMEM_TC>>>(
        y, W_fc, b_fc, nullptr, out, M, OO, HH, 0);
}